// round 7
// baseline (speedup 1.0000x reference)
#include <cuda_runtime.h>
#include <math.h>
#include <stdint.h>

// Problem constants (fixed by setup_inputs)
#define B_   64
#define L_   680
#define C_   1024
#define NSEG 10

__constant__ int       c_start[NSEG] = {0,1,5,14,30,55,91,155,255,424};
__constant__ int       c_len[NSEG]   = {1,4,9,16,25,36,64,100,169,256};
__constant__ long long c_base[NSEG]  = {0LL,8192LL,73728LL,294912LL,819200LL,
                                        1843200LL,3612672LL,7282688LL,13836288LL,26296320LL};
// Tile prefix tables for BM=128 tiles:
//   mtiles_i = ceil(64*len_i/128) = {1,2,5,8,13,18,32,50,85,128}
//   scores tiles_i = mtiles_i*(i+1); attnv tiles_i = mtiles_i*8
__constant__ int c_stp[NSEG + 1] = {0,1,5,20,52,117,225,449,849,1614,2894};
__constant__ int c_atp[NSEG + 1] = {0,8,24,64,128,232,376,632,1032,1712,2736};

// Static device scratch
__device__ float g_Q  [44564480];   // 43520 x 1024
__device__ float g_KV [2621440];    // 1280 x 2048  (cols 0-1023: K, 1024-2047: V)
__device__ float g_wkv[2097152];    // 1024 x 2048  (Wk | Wv)
__device__ float g_S  [47267840];   // segment-packed scores/attn
__device__ float g_MC [44564480];   // mem_combined, 43520 x 1024
__device__ float g_mid[5570560];    // 43520 x 128 (mid_k | mid_v)
__device__ float g_w12[131072];     // 1024 x 128 (wk1 | wv1)
__device__ float g_b12[128];        // bk1 | bv1

#define SM_STRIDE 136   // mod 32 = 8 -> conflict-free fragment reads

__device__ __forceinline__ float f2tf32(float x) {
    uint32_t r;
    asm("cvt.rna.tf32.f32 %0, %1;" : "=r"(r) : "f"(x));
    float out;
    asm("mov.b32 %0, %1;" : "=f"(out) : "r"(r));
    return out;
}

// ---------------------------------------------------------------------------
// TF32 GEMM core: one 128x128 C-tile at (m0, n0), K-loop over full K.
//   A: [M,K] row-major (lda); alen>0 => row remap (m/alen)*680+astart+(m%alen)
//   B: NN = [K,N] (ldb), NT = [N,K] (ldb)
//   C: [M,N] (ldc); clen>0 => row remap
// 128 threads, 4 warps, warp tile 64x64: wm=(w&1)*64, wn=(w>>1)*64.
// Per warp per 8-k substep: 32 LDS.32 + 32 m16n8k8 MMA (1:1).
// 128-thread CTAs guarantee 2 CTAs/SM at any regcount <=256 -> the two
// resident CTAs cover each other's barrier/prologue/epilogue bubbles.
// ---------------------------------------------------------------------------
template<int TRANSB>
__device__ __forceinline__ void gemm_core(
    const float* __restrict__ A, int lda,
    const float* __restrict__ B, int ldb,
    float* __restrict__ C, int ldc,
    int M, int N, int K,
    int alen, int astart, int clen, int cstart,
    const float* __restrict__ bias,
    const float* __restrict__ gate_logit,
    int m0, int n0)
{
    __shared__ float As[2][16][SM_STRIDE];
    __shared__ float Bs[2][16][SM_STRIDE];

    const int tid  = threadIdx.x;
    const int lane = tid & 31;
    const int w    = tid >> 5;
    const int wm   = (w & 1) * 64;
    const int wn   = (w >> 1) * 64;
    const int g    = lane >> 2;     // 0..7
    const int t4   = lane & 3;      // 0..3

    float acc[4][8][4];
    #pragma unroll
    for (int i = 0; i < 4; i++)
        #pragma unroll
        for (int j = 0; j < 8; j++)
            #pragma unroll
            for (int k = 0; k < 4; k++) acc[i][j][k] = 0.f;

    // ---- A: thread loads the full 16-k slice of row m0+tid ----
    const int am   = m0 + tid;
    const bool amOK = am < M;
    long long arow = (alen > 0)
        ? (long long)(am / alen) * L_ + astart + (am % alen)
        : (long long)am;
    const float* Aptr = A + arow * (long long)lda;

    // ---- B ----
    const float* Bptr;
    bool bOK;
    int b_r, b_c;
    if (!TRANSB) {
        // [K,N] tile 16x128: thread covers row tid>>3, cols (tid&7)*16..+15
        int kr = tid >> 3;
        int cn = (tid & 7) * 16;
        bOK  = (n0 + cn) < N;
        Bptr = B + (long long)kr * ldb + n0 + cn;
        b_r = kr; b_c = cn;
    } else {
        // [N,K] tile 128x16: thread covers row n0+tid, full 16 k
        bOK  = (n0 + tid) < N;
        Bptr = B + (long long)(n0 + tid) * ldb;
        b_r = 0; b_c = tid;
    }

    float4 ra[4], rb[4];
    const float4 z4 = make_float4(0.f, 0.f, 0.f, 0.f);

    auto ldg = [&](int k0) {
        if (amOK) {
            #pragma unroll
            for (int i = 0; i < 4; i++) ra[i] = *(const float4*)(Aptr + k0 + i * 4);
        } else { ra[0] = z4; ra[1] = z4; ra[2] = z4; ra[3] = z4; }
        if (!TRANSB) {
            const float* p = Bptr + (long long)k0 * ldb;
            if (bOK) {
                #pragma unroll
                for (int i = 0; i < 4; i++) rb[i] = *(const float4*)(p + i * 4);
            } else { rb[0] = z4; rb[1] = z4; rb[2] = z4; rb[3] = z4; }
        } else {
            if (bOK) {
                #pragma unroll
                for (int i = 0; i < 4; i++) rb[i] = *(const float4*)(Bptr + k0 + i * 4);
            } else { rb[0] = z4; rb[1] = z4; rb[2] = z4; rb[3] = z4; }
        }
    };

    auto sts = [&](int buf) {
        {
            const float* v = (const float*)ra;
            #pragma unroll
            for (int j = 0; j < 16; j++)
                As[buf][j][tid] = f2tf32(v[j]);
        }
        if (!TRANSB) {
            #pragma unroll
            for (int i = 0; i < 4; i++) {
                float4 c = make_float4(f2tf32(rb[i].x), f2tf32(rb[i].y),
                                       f2tf32(rb[i].z), f2tf32(rb[i].w));
                *(float4*)&Bs[buf][b_r][b_c + i * 4] = c;
            }
        } else {
            const float* v = (const float*)rb;
            #pragma unroll
            for (int j = 0; j < 16; j++)
                Bs[buf][j][b_c] = f2tf32(v[j]);
        }
    };

    auto compute = [&](int buf) {
        #pragma unroll
        for (int kb = 0; kb < 16; kb += 8) {
            uint32_t af[4][4], bf[8][2];
            #pragma unroll
            for (int mi = 0; mi < 4; mi++) {
                int mb = wm + mi * 16;
                af[mi][0] = __float_as_uint(As[buf][kb + t4    ][mb + g    ]);
                af[mi][1] = __float_as_uint(As[buf][kb + t4    ][mb + g + 8]);
                af[mi][2] = __float_as_uint(As[buf][kb + t4 + 4][mb + g    ]);
                af[mi][3] = __float_as_uint(As[buf][kb + t4 + 4][mb + g + 8]);
            }
            #pragma unroll
            for (int ni = 0; ni < 8; ni++) {
                int nb = wn + ni * 8;
                bf[ni][0] = __float_as_uint(Bs[buf][kb + t4    ][nb + g]);
                bf[ni][1] = __float_as_uint(Bs[buf][kb + t4 + 4][nb + g]);
            }
            #pragma unroll
            for (int mi = 0; mi < 4; mi++)
                #pragma unroll
                for (int ni = 0; ni < 8; ni++) {
                    asm volatile(
                        "mma.sync.aligned.m16n8k8.row.col.f32.tf32.tf32.f32 "
                        "{%0,%1,%2,%3},{%4,%5,%6,%7},{%8,%9},{%0,%1,%2,%3};"
                        : "+f"(acc[mi][ni][0]), "+f"(acc[mi][ni][1]),
                          "+f"(acc[mi][ni][2]), "+f"(acc[mi][ni][3])
                        : "r"(af[mi][0]), "r"(af[mi][1]),
                          "r"(af[mi][2]), "r"(af[mi][3]),
                          "r"(bf[ni][0]), "r"(bf[ni][1]));
                }
        }
    };

    // ---- pipelined main loop ----
    ldg(0);
    sts(0);
    __syncthreads();
    int cur = 0;
    for (int k0 = 16;; k0 += 16) {
        bool more = k0 < K;
        if (more) ldg(k0);
        compute(cur);
        if (!more) break;
        sts(cur ^ 1);
        __syncthreads();
        cur ^= 1;
    }

    // ---- epilogue ----
    float gate = 1.0f;
    if (gate_logit) gate = 1.0f / (1.0f + expf(-(*gate_logit)));

    #pragma unroll
    for (int mi = 0; mi < 4; mi++) {
        #pragma unroll
        for (int rr = 0; rr < 2; rr++) {
            int m = m0 + wm + mi * 16 + g + rr * 8;
            if (m >= M) continue;
            long long crow = (clen > 0)
                ? (long long)(m / clen) * L_ + cstart + (m % clen)
                : (long long)m;
            float* cp = C + crow * (long long)ldc;
            #pragma unroll
            for (int ni = 0; ni < 8; ni++) {
                int n = n0 + wn + ni * 8 + t4 * 2;
                if (n >= N) continue;
                float v0 = acc[mi][ni][rr * 2 + 0];
                float v1 = acc[mi][ni][rr * 2 + 1];
                if (bias) { v0 += bias[n]; v1 += bias[n + 1]; }
                cp[n]     = v0 * gate;
                cp[n + 1] = v1 * gate;
            }
        }
    }
}

// ---------------------------------------------------------------------------
// Dense GEMM wrapper (NN)
// ---------------------------------------------------------------------------
__global__ void tgemm_nn(const float* __restrict__ A, int lda,
                         const float* __restrict__ B, int ldb,
                         float* __restrict__ C, int ldc,
                         int M, int N, int K,
                         const float* __restrict__ bias,
                         const float* __restrict__ gate_logit)
{
    gemm_core<0>(A, lda, B, ldb, C, ldc, M, N, K, 0, 0, 0, 0,
                 bias, gate_logit, blockIdx.y * 128, blockIdx.x * 128);
}

// Fused scores kernel: all 10 segments, one launch (2894 tiles)
__global__ void scores_kernel()
{
    int t = blockIdx.x;
    int seg = 0;
    #pragma unroll
    for (int i = 1; i < NSEG; i++) if (t >= c_stp[i]) seg = i;
    int local = t - c_stp[seg];
    int nt = seg + 1;
    int tm = local / nt;
    int tn = local - tm * nt;
    int len = c_len[seg], start = c_start[seg];
    int Nseg = 128 * nt, Mseg = 64 * len;
    gemm_core<1>(g_Q, C_, g_KV, 2048, g_S + c_base[seg], Nseg,
                 Mseg, Nseg, C_, len, start, 0, 0, nullptr, nullptr,
                 tm * 128, tn * 128);
}

// Fused attn@V kernel: all 10 segments, one launch (2736 tiles)
__global__ void attnv_kernel()
{
    int t = blockIdx.x;
    int seg = 0;
    #pragma unroll
    for (int i = 1; i < NSEG; i++) if (t >= c_atp[i]) seg = i;
    int local = t - c_atp[seg];
    int tm = local >> 3;
    int tn = local & 7;
    int len = c_len[seg], start = c_start[seg];
    int Nseg = 128 * (seg + 1), Mseg = 64 * len;
    gemm_core<0>(g_S + c_base[seg], Nseg, g_KV + 1024, 2048, g_MC, C_,
                 Mseg, C_, Nseg, 0, 0, len, start, nullptr, nullptr,
                 tm * 128, tn * 128);
}

// ---------------------------------------------------------------------------
// Row softmax over segment-packed g_S; scale = (1/32)/clip(exp(log_temp))
// ---------------------------------------------------------------------------
__global__ void softmax_kernel(const float* __restrict__ log_temp)
{
    int row = blockIdx.x;           // b*L + l
    int b = row / L_;
    int l = row - b * L_;

    int seg = 0;
    #pragma unroll
    for (int s2 = 1; s2 < NSEG; s2++)
        if (l >= c_start[s2]) seg = s2;

    const int n   = 128 * (seg + 1);
    const int len = c_len[seg];
    float* p = g_S + c_base[seg] + ((long long)b * len + (l - c_start[seg])) * (long long)n;

    float t = expf(*log_temp);
    t = fminf(fmaxf(t, 0.05f), 1.0f);
    const float scale = (1.0f / 32.0f) / t;

    __shared__ float sh[8];
    const int lane = threadIdx.x & 31;
    const int w    = threadIdx.x >> 5;

    float m = -1e30f;
    for (int j = threadIdx.x; j < n; j += 256) m = fmaxf(m, p[j] * scale);
    #pragma unroll
    for (int o = 16; o; o >>= 1) m = fmaxf(m, __shfl_xor_sync(0xffffffffu, m, o));
    if (lane == 0) sh[w] = m;
    __syncthreads();
    m = sh[lane & 7];
    #pragma unroll
    for (int o = 4; o; o >>= 1) m = fmaxf(m, __shfl_xor_sync(0xffffffffu, m, o));

    float sum = 0.f;
    for (int j = threadIdx.x; j < n; j += 256) {
        float e = expf(p[j] * scale - m);
        p[j] = e;
        sum += e;
    }
    #pragma unroll
    for (int o = 16; o; o >>= 1) sum += __shfl_xor_sync(0xffffffffu, sum, o);
    __syncthreads();
    if (lane == 0) sh[w] = sum;
    __syncthreads();
    sum = sh[lane & 7];
    #pragma unroll
    for (int o = 4; o; o >>= 1) sum += __shfl_xor_sync(0xffffffffu, sum, o);

    const float inv = 1.0f / sum;
    for (int j = threadIdx.x; j < n; j += 256) p[j] *= inv;
}

// Pack wk1|wv1 -> g_w12 [1024x128], bk1|bv1 -> g_b12 [128]
__global__ void pack_w12_kernel(const float* __restrict__ wk1,
                                const float* __restrict__ wv1,
                                const float* __restrict__ bk1,
                                const float* __restrict__ bv1)
{
    int idx = blockIdx.x * 256 + threadIdx.x;
    if (idx < 1024 * 64) {
        int k = idx >> 6, j = idx & 63;
        g_w12[k * 128 + j]      = wk1[idx];
        g_w12[k * 128 + 64 + j] = wv1[idx];
    }
    if (idx < 64) {
        g_b12[idx]      = bk1[idx];
        g_b12[64 + idx] = bv1[idx];
    }
}

// Pack Wk|Wv -> g_wkv [1024 x 2048]
__global__ void pack_wkv_kernel(const float* __restrict__ Wk,
                                const float* __restrict__ Wv)
{
    int idx = blockIdx.x * 256 + threadIdx.x;   // over 1024*1024
    int k = idx >> 10, j = idx & 1023;
    g_wkv[k * 2048 + j]        = Wk[idx];
    g_wkv[k * 2048 + 1024 + j] = Wv[idx];
}

__global__ void tail_kernel(float* out, long long off)
{
    if (threadIdx.x < 2) out[off + threadIdx.x] = 0.f;
}

// ---------------------------------------------------------------------------
extern "C" void kernel_launch(void* const* d_in, const int* in_sizes, int n_in,
                              void* d_out, int out_size)
{
    const float* x   = (const float*)d_in[0];
    const float* mem = (const float*)d_in[1];
    const float* Wq  = (const float*)d_in[2];
    const float* Wk  = (const float*)d_in[3];
    const float* Wv  = (const float*)d_in[4];
    const float* wk1 = (const float*)d_in[5];
    const float* bk1 = (const float*)d_in[6];
    const float* wk2 = (const float*)d_in[7];
    const float* bk2 = (const float*)d_in[8];
    const float* wv1 = (const float*)d_in[9];
    const float* bv1 = (const float*)d_in[10];
    const float* wv2 = (const float*)d_in[11];
    const float* bv2 = (const float*)d_in[12];
    const float* gk  = (const float*)d_in[13];
    const float* gv  = (const float*)d_in[14];
    const float* lt  = (const float*)d_in[15];
    float* out = (float*)d_out;

    float *Q, *KV, *wkv, *MC, *mid, *w12, *b12;
    cudaGetSymbolAddress((void**)&Q,   g_Q);
    cudaGetSymbolAddress((void**)&KV,  g_KV);
    cudaGetSymbolAddress((void**)&wkv, g_wkv);
    cudaGetSymbolAddress((void**)&MC,  g_MC);
    cudaGetSymbolAddress((void**)&mid, g_mid);
    cudaGetSymbolAddress((void**)&w12, g_w12);
    cudaGetSymbolAddress((void**)&b12, g_b12);

    // 0) pack weights
    pack_w12_kernel<<<256, 256>>>(wk1, wv1, bk1, bv1);
    pack_wkv_kernel<<<4096, 256>>>(Wk, Wv);

    // 1) projections (BM=128, BN=128; 128 threads)
    tgemm_nn<<<dim3(C_ / 128, (B_ * L_) / 128), 128>>>(
        x,   C_, Wq, C_, Q,  C_, B_ * L_, C_, C_, nullptr, nullptr);
    // fused K|V projection: [1280 x 1024] @ [1024 x 2048] -> g_KV
    tgemm_nn<<<dim3(2048 / 128, 1280 / 128), 128>>>(
        mem, C_, wkv, 2048, KV, 2048, NSEG * 128, 2048, C_, nullptr, nullptr);

    // 2) all score GEMMs, one launch
    scores_kernel<<<2894, 128>>>();

    // 3) softmax in-place
    softmax_kernel<<<B_ * L_, 256>>>(lt);

    // 4) all attn @ V GEMMs, one launch
    attnv_kernel<<<2736, 128>>>();

    // 5) fused mid GEMM: mid = MC @ [wk1|wv1] + [bk1|bv1]   (43520 x 128, K=1024)
    tgemm_nn<<<dim3(1, (B_ * L_) / 128), 128>>>(
        MC, C_, w12, 128, mid, 128, B_ * L_, 128, C_, b12, nullptr);

    // 6) up-projections with gate epilogue (K=64, A lda=128)
    tgemm_nn<<<dim3(C_ / 128, (B_ * L_) / 128), 128>>>(
        mid,      128, wk2, C_, out, C_, B_ * L_, C_, 64, bk2, gk);
    tgemm_nn<<<dim3(C_ / 128, (B_ * L_) / 128), 128>>>(
        mid + 64, 128, wv2, C_, out + (long long)B_ * L_ * C_, C_,
        B_ * L_, C_, 64, bv2, gv);

    // 7) trailing two scalar zeros
    tail_kernel<<<1, 32>>>(out, 2LL * B_ * L_ * C_);
}

// round 8
// speedup vs baseline: 1.1910x; 1.1910x over previous
#include <cuda_runtime.h>
#include <math.h>
#include <stdint.h>

// Problem constants (fixed by setup_inputs)
#define B_   64
#define L_   680
#define C_   1024
#define NSEG 10

__constant__ int       c_start[NSEG] = {0,1,5,14,30,55,91,155,255,424};
__constant__ int       c_len[NSEG]   = {1,4,9,16,25,36,64,100,169,256};
__constant__ long long c_base[NSEG]  = {0LL,8192LL,73728LL,294912LL,819200LL,
                                        1843200LL,3612672LL,7282688LL,13836288LL,26296320LL};
// Tile prefix tables for BM=256 tiles:
//   mtiles_i = ceil(64*len_i/256) = {1,1,3,4,7,9,16,25,43,64}
__constant__ int c_stp[NSEG + 1] = {0,1,3,12,28,63,117,229,429,816,1456};
__constant__ int c_atp[NSEG + 1] = {0,8,16,40,72,128,200,328,528,872,1384};

// Static device scratch
__device__ float g_Q   [44564480];  // 43520 x 1024 (tf32-rounded Q)
__device__ float g_KV  [2621440];   // 1280 x 2048 (K | V, tf32-rounded)
__device__ float g_wkv [2097152];   // 1024 x 2048 (Wk | Wv, rounded)
__device__ float g_S   [47267840];  // rounded-x first, then scores/attn
__device__ float g_MC  [44564480];  // mem_combined (rounded)
__device__ float g_mid [5570560];   // 43520 x 128 (rounded, mid_k | mid_v)
__device__ float g_w12 [131072];    // 1024 x 128 (wk1 | wv1, rounded)
__device__ float g_b12 [128];       // bk1 | bv1 (fp32)
__device__ float g_wq  [1048576];   // Wq rounded
__device__ float g_w34 [131072];    // wk2 (0..65535) | wv2 (65536..) rounded
__device__ float g_memr[1310720];   // mem rounded

// Smem staging (per stage): A 256 rows x stride 20 = 5120 floats,
//                           B max(16*136, 128*20) = 2560 floats
#define A_ROW_STRIDE 20
#define BNN_STRIDE   136
#define BNT_STRIDE   20
#define A_STAGE_FLOATS 5120
#define B_STAGE_FLOATS 2560
#define STAGE_FLOATS   (A_STAGE_FLOATS + B_STAGE_FLOATS)   // 7680
#define STAGE_BYTES    (STAGE_FLOATS * 4)                  // 30720
#define SMEM_BYTES     (3 * STAGE_BYTES)                   // 92160

__device__ __forceinline__ float f2tf32(float x) {
    uint32_t r;
    asm("cvt.rna.tf32.f32 %0, %1;" : "=r"(r) : "f"(x));
    float out;
    asm("mov.b32 %0, %1;" : "=f"(out) : "r"(r));
    return out;
}

__device__ __forceinline__ void cp16(uint32_t dst, const float* src, int szbytes) {
    asm volatile("cp.async.cg.shared.global [%0], [%1], 16, %2;"
                 :: "r"(dst), "l"(src), "r"(szbytes));
}
__device__ __forceinline__ void cp_commit() {
    asm volatile("cp.async.commit_group;");
}
__device__ __forceinline__ void cp_wait1() {
    asm volatile("cp.async.wait_group 1;");
}
__device__ __forceinline__ void cp_wait0() {
    asm volatile("cp.async.wait_group 0;");
}

// ---------------------------------------------------------------------------
// TF32 GEMM core: one 256x128 C-tile at (m0, n0). Inputs MUST be pre-rounded
// to tf32. cp.async 3-stage pipeline, no in-loop conversion or staging.
//   A: [M,K] (lda); alen>0 => row remap (m/alen)*680+astart+(m%alen)
//   B: NN = [K,N] (ldb), NT = [N,K] (ldb); N must be a multiple of 128.
//   C: [M,N] (ldc); clen>0 => row remap. K % 16 == 0.
// 256 threads, 8 warps, 64x64 warp tile, m16n8k8 tf32 mma.
// ---------------------------------------------------------------------------
template<int TRANSB>
__device__ __forceinline__ void gemm_core(
    const float* __restrict__ A, int lda,
    const float* __restrict__ B, int ldb,
    float* __restrict__ C, int ldc,
    int M, int N, int K,
    int alen, int astart, int clen, int cstart,
    const float* __restrict__ bias,
    const float* __restrict__ gate_logit,
    int m0, int n0, bool round_out)
{
    extern __shared__ float smbuf[];
    const uint32_t smem_u32 = (uint32_t)__cvta_generic_to_shared(smbuf);

    const int tid  = threadIdx.x;
    const int lane = tid & 31;
    const int w    = tid >> 5;
    const int wm   = (w & 3) * 64;
    const int wn   = (w >> 2) * 64;
    const int g    = lane >> 2;
    const int t4   = lane & 3;

    float acc[4][8][4];
    #pragma unroll
    for (int i = 0; i < 4; i++)
        #pragma unroll
        for (int j = 0; j < 8; j++)
            #pragma unroll
            for (int k = 0; k < 4; k++) acc[i][j][k] = 0.f;

    // ---- A: thread owns row m0+tid (16 k per stage, 4 cp.async) ----
    const int am    = m0 + tid;
    const bool amOK = am < M;
    const int amc   = amOK ? am : 0;
    long long arow = (alen > 0)
        ? (long long)(amc / alen) * L_ + astart + (amc % alen)
        : (long long)amc;
    const float* Aptr = A + arow * (long long)lda;
    const int a_sz = amOK ? 16 : 0;
    const uint32_t a_dst = smem_u32 + tid * (A_ROW_STRIDE * 4);

    // ---- B setup ----
    const float* Bbase;
    uint32_t b_dst;
    int b_ldmul = 0;
    if (!TRANSB) {
        int kr = tid >> 4;            // 0..15
        int cn = (tid & 15) * 8;      // 0..120
        Bbase = B + (long long)kr * ldb + n0 + cn;   // + k0*ldb at issue
        b_dst = smem_u32 + (A_STAGE_FLOATS + kr * BNN_STRIDE + cn) * 4;
        b_ldmul = ldb;
    } else {
        int bn = tid >> 1;            // 0..127
        int kh = (tid & 1) * 8;
        Bbase = B + (long long)(n0 + bn) * ldb + kh; // + k0 at issue
        b_dst = smem_u32 + (A_STAGE_FLOATS + bn * BNT_STRIDE + kh) * 4;
    }

    auto issue = [&](int s, int k0) {
        uint32_t soff = (uint32_t)s * STAGE_BYTES;
        const float* ap = Aptr + k0;
        uint32_t ad = a_dst + soff;
        cp16(ad,      ap,      a_sz);
        cp16(ad + 16, ap + 4,  a_sz);
        cp16(ad + 32, ap + 8,  a_sz);
        cp16(ad + 48, ap + 12, a_sz);
        uint32_t bd = b_dst + soff;
        if (!TRANSB) {
            const float* bp = Bbase + (long long)k0 * b_ldmul;
            cp16(bd,      bp,     16);
            cp16(bd + 16, bp + 4, 16);
        } else {
            const float* bp = Bbase + k0;
            cp16(bd,      bp,     16);
            cp16(bd + 16, bp + 4, 16);
        }
        cp_commit();
    };

    auto compute = [&](int s) {
        const float* Ass = smbuf + s * STAGE_FLOATS;                  // [m][16] stride 20
        const float* Bss = smbuf + s * STAGE_FLOATS + A_STAGE_FLOATS; // NN [k][n] / NT [n][16]
        #pragma unroll
        for (int kb = 0; kb < 16; kb += 8) {
            uint32_t af[4][4], bf[8][2];
            #pragma unroll
            for (int mi = 0; mi < 4; mi++) {
                int rlo = (wm + mi * 16 + g) * A_ROW_STRIDE;
                int rhi = rlo + 8 * A_ROW_STRIDE;
                af[mi][0] = __float_as_uint(Ass[rlo + kb + t4]);
                af[mi][1] = __float_as_uint(Ass[rhi + kb + t4]);
                af[mi][2] = __float_as_uint(Ass[rlo + kb + t4 + 4]);
                af[mi][3] = __float_as_uint(Ass[rhi + kb + t4 + 4]);
            }
            #pragma unroll
            for (int ni = 0; ni < 8; ni++) {
                int nb = wn + ni * 8 + g;
                if (!TRANSB) {
                    bf[ni][0] = __float_as_uint(Bss[(kb + t4) * BNN_STRIDE + nb]);
                    bf[ni][1] = __float_as_uint(Bss[(kb + t4 + 4) * BNN_STRIDE + nb]);
                } else {
                    bf[ni][0] = __float_as_uint(Bss[nb * BNT_STRIDE + kb + t4]);
                    bf[ni][1] = __float_as_uint(Bss[nb * BNT_STRIDE + kb + t4 + 4]);
                }
            }
            #pragma unroll
            for (int mi = 0; mi < 4; mi++)
                #pragma unroll
                for (int ni = 0; ni < 8; ni++) {
                    asm volatile(
                        "mma.sync.aligned.m16n8k8.row.col.f32.tf32.tf32.f32 "
                        "{%0,%1,%2,%3},{%4,%5,%6,%7},{%8,%9},{%0,%1,%2,%3};"
                        : "+f"(acc[mi][ni][0]), "+f"(acc[mi][ni][1]),
                          "+f"(acc[mi][ni][2]), "+f"(acc[mi][ni][3])
                        : "r"(af[mi][0]), "r"(af[mi][1]),
                          "r"(af[mi][2]), "r"(af[mi][3]),
                          "r"(bf[ni][0]), "r"(bf[ni][1]));
                }
        }
    };

    // ---- 3-stage pipelined main loop ----
    const int T = K >> 4;
    issue(0, 0);
    if (T > 1) issue(1, 16);
    for (int i = 0; i < T; i++) {
        if (i + 1 < T) cp_wait1(); else cp_wait0();
        __syncthreads();
        if (i + 2 < T) issue((i + 2) % 3, (i + 2) * 16);
        compute(i % 3);
        if (i + 1 < T) __syncthreads();   // protect buffer reuse ordering
    }

    // ---- epilogue ----
    float gate = 1.0f;
    if (gate_logit) gate = 1.0f / (1.0f + expf(-(*gate_logit)));

    #pragma unroll
    for (int mi = 0; mi < 4; mi++) {
        #pragma unroll
        for (int rr = 0; rr < 2; rr++) {
            int m = m0 + wm + mi * 16 + g + rr * 8;
            if (m >= M) continue;
            long long crow = (clen > 0)
                ? (long long)(m / clen) * L_ + cstart + (m % clen)
                : (long long)m;
            float* cp = C + crow * (long long)ldc;
            #pragma unroll
            for (int ni = 0; ni < 8; ni++) {
                int n = n0 + wn + ni * 8 + t4 * 2;
                if (n >= N) continue;
                float v0 = acc[mi][ni][rr * 2 + 0];
                float v1 = acc[mi][ni][rr * 2 + 1];
                if (bias) { v0 += bias[n]; v1 += bias[n + 1]; }
                v0 *= gate; v1 *= gate;
                if (round_out) { v0 = f2tf32(v0); v1 = f2tf32(v1); }
                cp[n]     = v0;
                cp[n + 1] = v1;
            }
        }
    }
}

// ---------------------------------------------------------------------------
__global__ void tgemm_nn(const float* __restrict__ A, int lda,
                         const float* __restrict__ B, int ldb,
                         float* __restrict__ C, int ldc,
                         int M, int N, int K,
                         const float* __restrict__ bias,
                         const float* __restrict__ gate_logit,
                         int round_out)
{
    gemm_core<0>(A, lda, B, ldb, C, ldc, M, N, K, 0, 0, 0, 0,
                 bias, gate_logit, blockIdx.y * 256, blockIdx.x * 128,
                 round_out != 0);
}

// Fused scores kernel: all 10 segments, one launch (1456 tiles). NOT rounded.
__global__ void scores_kernel()
{
    int t = blockIdx.x;
    int seg = 0;
    #pragma unroll
    for (int i = 1; i < NSEG; i++) if (t >= c_stp[i]) seg = i;
    int local = t - c_stp[seg];
    int nt = seg + 1;
    int tm = local / nt;
    int tn = local - tm * nt;
    int len = c_len[seg], start = c_start[seg];
    int Nseg = 128 * nt, Mseg = 64 * len;
    gemm_core<1>(g_Q, C_, g_KV, 2048, g_S + c_base[seg], Nseg,
                 Mseg, Nseg, C_, len, start, 0, 0, nullptr, nullptr,
                 tm * 256, tn * 128, false);
}

// Fused attn@V kernel: all 10 segments, one launch (1384 tiles). Rounded (-> MC).
__global__ void attnv_kernel()
{
    int t = blockIdx.x;
    int seg = 0;
    #pragma unroll
    for (int i = 1; i < NSEG; i++) if (t >= c_atp[i]) seg = i;
    int local = t - c_atp[seg];
    int tm = local >> 3;
    int tn = local & 7;
    int len = c_len[seg], start = c_start[seg];
    int Nseg = 128 * (seg + 1), Mseg = 64 * len;
    gemm_core<0>(g_S + c_base[seg], Nseg, g_KV + 1024, 2048, g_MC, C_,
                 Mseg, C_, Nseg, 0, 0, len, start, nullptr, nullptr,
                 tm * 256, tn * 128, true);
}

// ---------------------------------------------------------------------------
// Row softmax; scale = (1/32)/clip(exp(log_temp)); output tf32-rounded.
// ---------------------------------------------------------------------------
__global__ void softmax_kernel(const float* __restrict__ log_temp)
{
    int row = blockIdx.x;           // b*L + l
    int b = row / L_;
    int l = row - b * L_;

    int seg = 0;
    #pragma unroll
    for (int s2 = 1; s2 < NSEG; s2++)
        if (l >= c_start[s2]) seg = s2;

    const int n   = 128 * (seg + 1);
    const int len = c_len[seg];
    float* p = g_S + c_base[seg] + ((long long)b * len + (l - c_start[seg])) * (long long)n;

    float t = expf(*log_temp);
    t = fminf(fmaxf(t, 0.05f), 1.0f);
    const float scale = (1.0f / 32.0f) / t;

    __shared__ float sh[8];
    const int lane = threadIdx.x & 31;
    const int w    = threadIdx.x >> 5;

    float m = -1e30f;
    for (int j = threadIdx.x; j < n; j += 256) m = fmaxf(m, p[j] * scale);
    #pragma unroll
    for (int o = 16; o; o >>= 1) m = fmaxf(m, __shfl_xor_sync(0xffffffffu, m, o));
    if (lane == 0) sh[w] = m;
    __syncthreads();
    m = sh[lane & 7];
    #pragma unroll
    for (int o = 4; o; o >>= 1) m = fmaxf(m, __shfl_xor_sync(0xffffffffu, m, o));

    float sum = 0.f;
    for (int j = threadIdx.x; j < n; j += 256) {
        float e = expf(p[j] * scale - m);
        p[j] = e;
        sum += e;
    }
    #pragma unroll
    for (int o = 16; o; o >>= 1) sum += __shfl_xor_sync(0xffffffffu, sum, o);
    __syncthreads();
    if (lane == 0) sh[w] = sum;
    __syncthreads();
    sum = sh[lane & 7];
    #pragma unroll
    for (int o = 4; o; o >>= 1) sum += __shfl_xor_sync(0xffffffffu, sum, o);

    const float inv = 1.0f / sum;
    for (int j = threadIdx.x; j < n; j += 256) p[j] = f2tf32(p[j] * inv);
}

// ---------------------------------------------------------------------------
// Pre-round / pack kernels
// ---------------------------------------------------------------------------
__global__ void round_copy_kernel(const float* __restrict__ src,
                                  float* __restrict__ dst, int n4)
{
    int i = blockIdx.x * 256 + threadIdx.x;
    if (i < n4) {
        float4 v = ((const float4*)src)[i];
        v.x = f2tf32(v.x); v.y = f2tf32(v.y);
        v.z = f2tf32(v.z); v.w = f2tf32(v.w);
        ((float4*)dst)[i] = v;
    }
}

__global__ void pack_w12_kernel(const float* __restrict__ wk1,
                                const float* __restrict__ wv1,
                                const float* __restrict__ bk1,
                                const float* __restrict__ bv1)
{
    int idx = blockIdx.x * 256 + threadIdx.x;
    if (idx < 1024 * 64) {
        int k = idx >> 6, j = idx & 63;
        g_w12[k * 128 + j]      = f2tf32(wk1[idx]);
        g_w12[k * 128 + 64 + j] = f2tf32(wv1[idx]);
    }
    if (idx < 64) {
        g_b12[idx]      = bk1[idx];
        g_b12[64 + idx] = bv1[idx];
    }
}

__global__ void pack_wkv_kernel(const float* __restrict__ Wk,
                                const float* __restrict__ Wv)
{
    int idx = blockIdx.x * 256 + threadIdx.x;   // over 1024*1024
    int k = idx >> 10, j = idx & 1023;
    g_wkv[k * 2048 + j]        = f2tf32(Wk[idx]);
    g_wkv[k * 2048 + 1024 + j] = f2tf32(Wv[idx]);
}

__global__ void tail_kernel(float* out, long long off)
{
    if (threadIdx.x < 2) out[off + threadIdx.x] = 0.f;
}

// ---------------------------------------------------------------------------
extern "C" void kernel_launch(void* const* d_in, const int* in_sizes, int n_in,
                              void* d_out, int out_size)
{
    const float* x   = (const float*)d_in[0];
    const float* mem = (const float*)d_in[1];
    const float* Wq  = (const float*)d_in[2];
    const float* Wk  = (const float*)d_in[3];
    const float* Wv  = (const float*)d_in[4];
    const float* wk1 = (const float*)d_in[5];
    const float* bk1 = (const float*)d_in[6];
    const float* wk2 = (const float*)d_in[7];
    const float* bk2 = (const float*)d_in[8];
    const float* wv1 = (const float*)d_in[9];
    const float* bv1 = (const float*)d_in[10];
    const float* wv2 = (const float*)d_in[11];
    const float* bv2 = (const float*)d_in[12];
    const float* gk  = (const float*)d_in[13];
    const float* gv  = (const float*)d_in[14];
    const float* lt  = (const float*)d_in[15];
    float* out = (float*)d_out;

    float *Q, *KV, *wkv, *S, *MC, *mid, *w12, *b12, *wq, *w34, *memr;
    cudaGetSymbolAddress((void**)&Q,    g_Q);
    cudaGetSymbolAddress((void**)&KV,   g_KV);
    cudaGetSymbolAddress((void**)&wkv,  g_wkv);
    cudaGetSymbolAddress((void**)&S,    g_S);
    cudaGetSymbolAddress((void**)&MC,   g_MC);
    cudaGetSymbolAddress((void**)&mid,  g_mid);
    cudaGetSymbolAddress((void**)&w12,  g_w12);
    cudaGetSymbolAddress((void**)&b12,  g_b12);
    cudaGetSymbolAddress((void**)&wq,   g_wq);
    cudaGetSymbolAddress((void**)&w34,  g_w34);
    cudaGetSymbolAddress((void**)&memr, g_memr);

    cudaFuncSetAttribute(tgemm_nn,      cudaFuncAttributeMaxDynamicSharedMemorySize, SMEM_BYTES);
    cudaFuncSetAttribute(scores_kernel, cudaFuncAttributeMaxDynamicSharedMemorySize, SMEM_BYTES);
    cudaFuncSetAttribute(attnv_kernel,  cudaFuncAttributeMaxDynamicSharedMemorySize, SMEM_BYTES);

    // 0) pre-round inputs (x -> g_S scratch; freed when scores overwrite it)
    round_copy_kernel<<<43520, 256>>>(x,   S,    (B_ * L_ * C_) / 4);
    round_copy_kernel<<<1024,  256>>>(Wq,  wq,   (C_ * C_) / 4);
    round_copy_kernel<<<1280,  256>>>(mem, memr, (NSEG * 128 * C_) / 4);
    round_copy_kernel<<<64,    256>>>(wk2, w34,           (64 * C_) / 4);
    round_copy_kernel<<<64,    256>>>(wv2, w34 + 65536,   (64 * C_) / 4);
    pack_wkv_kernel<<<4096, 256>>>(Wk, Wv);
    pack_w12_kernel<<<256, 256>>>(wk1, wv1, bk1, bv1);

    // 1) projections
    tgemm_nn<<<dim3(C_ / 128, (B_ * L_) / 256), 256, SMEM_BYTES>>>(
        S, C_, wq, C_, Q, C_, B_ * L_, C_, C_, nullptr, nullptr, 1);
    tgemm_nn<<<dim3(2048 / 128, 1280 / 256), 256, SMEM_BYTES>>>(
        memr, C_, wkv, 2048, KV, 2048, NSEG * 128, 2048, C_, nullptr, nullptr, 1);

    // 2) all score GEMMs, one launch (overwrites rounded-x scratch)
    scores_kernel<<<1456, 256, SMEM_BYTES>>>();

    // 3) softmax in-place (rounds output)
    softmax_kernel<<<B_ * L_, 256>>>(lt);

    // 4) all attn @ V GEMMs, one launch
    attnv_kernel<<<1384, 256, SMEM_BYTES>>>();

    // 5) fused mid GEMM: mid = MC @ [wk1|wv1] + [bk1|bv1] (rounded)
    tgemm_nn<<<dim3(1, (B_ * L_) / 256), 256, SMEM_BYTES>>>(
        MC, C_, w12, 128, mid, 128, B_ * L_, 128, C_, b12, nullptr, 1);

    // 6) up-projections with gate epilogue (final outputs, NOT rounded)
    tgemm_nn<<<dim3(C_ / 128, (B_ * L_) / 256), 256, SMEM_BYTES>>>(
        mid,      128, w34,         C_, out, C_, B_ * L_, C_, 64, bk2, gk, 0);
    tgemm_nn<<<dim3(C_ / 128, (B_ * L_) / 256), 256, SMEM_BYTES>>>(
        mid + 64, 128, w34 + 65536, C_, out + (long long)B_ * L_ * C_, C_,
        B_ * L_, C_, 64, bv2, gv, 0);

    // 7) trailing two scalar zeros
    tail_kernel<<<1, 32>>>(out, 2LL * B_ * L_ * C_);
}